// round 6
// baseline (speedup 1.0000x reference)
#include <cuda_runtime.h>
#include <math.h>
#include <cstdint>

// B=8, A=1024, N=64, G=50, F=128
#define A_DIM 1024
#define F_DIM 128
#define G_DIM 50
#define LOG2F_CONST 0.6931471805599453f

// ---------------- device scratch ----------------
__device__ float g_xw[8 * A_DIM * F_DIM];                  // x @ W_in2f  (4 MB)
__device__ float g_y [8 * A_DIM * F_DIM];                  // pre-output  (4 MB)
__device__ __align__(16) float g_Wf1v[64 * F_DIM];         // W_f1 padded K=64, frag-permuted
__device__ __align__(16) float g_Wf2v[F_DIM * F_DIM];      // W_f2 frag-permuted

__device__ __forceinline__ float ssp(float x) {
    return fmaxf(x, 0.0f) + __logf(1.0f + __expf(-fabsf(x))) - LOG2F_CONST;
}
__device__ __forceinline__ float tf32r(float x) {
    uint32_t r;
    asm("cvt.rna.tf32.f32 %0, %1;" : "=r"(r) : "f"(x));
    return __uint_as_float(r);
}

// m16n8k8 row.col tf32 MMA. lane: gid=lane>>2, tig=lane&3
//   A: a0=(gid,tig) a1=(gid+8,tig) a2=(gid,tig+4) a3=(gid+8,tig+4)
//   B: b0=(k=tig,n=gid) b1=(k=tig+4,n=gid)
//   D: d0=(gid,2tig) d1=(gid,2tig+1) d2=(gid+8,2tig) d3=(gid+8,2tig+1)
__device__ __forceinline__ void mma8(float* d, const uint32_t* a, uint32_t b0, uint32_t b1) {
    asm volatile(
        "mma.sync.aligned.m16n8k8.row.col.f32.tf32.tf32.f32 "
        "{%0,%1,%2,%3}, {%4,%5,%6,%7}, {%8,%9}, {%0,%1,%2,%3};"
        : "+f"(d[0]), "+f"(d[1]), "+f"(d[2]), "+f"(d[3])
        : "r"(a[0]), "r"(a[1]), "r"(a[2]), "r"(a[3]), "r"(b0), "r"(b1));
}

// ---------------- SMEM layout ----------------
// frag layout: frag[tile][ks][lane][4]  (one float4 per lane = a0..a3)
#define OFF_B1   0        // b_f1 [128]f
#define OFF_B2   512      // b_f2 [128]f
#define OFF_NBR  1024     // nbr  [128]i
#define OFF_MSK  1536     // mask [128]f
#define OFF_FIJ  2048     // f_ij frags: 8 tiles x 8 ks x 32 x 4 f = 32768 B
#define OFF_H    34816    // h frags (8x16x32x4 = 65536 B)  /  Wm linear 128x130 f = 66560 B
#define WS 130            // Wm linear row stride (floats)
#define SMEM_TOTAL 101376

// ---------------------------------------------------------------------------
// prep: tf32-round + permute weights into fragment-vector order:
//   Wv[k][half][gid][ni] = W[k][half*64 + ni*8 + gid]
// ---------------------------------------------------------------------------
__global__ void prep_kernel(const float* __restrict__ W_f1, const float* __restrict__ W_f2) {
    int t = threadIdx.x;
    for (int i = t; i < 64 * F_DIM; i += blockDim.x) {
        int k = i >> 7, j = i & 127;
        int half = j >> 6, gid = (j >> 3) & 7, ni = j & 7;
        int src = half * 64 + ni * 8 + gid;
        g_Wf1v[i] = (k < G_DIM) ? tf32r(W_f1[k * F_DIM + src]) : 0.0f;
    }
    for (int i = t; i < F_DIM * F_DIM; i += blockDim.x) {
        int k = i >> 7, j = i & 127;
        int half = j >> 6, gid = (j >> 3) & 7, ni = j & 7;
        int src = half * 64 + ni * 8 + gid;
        g_Wf2v[i] = tf32r(W_f2[k * F_DIM + src]);
    }
}

// ---------------------------------------------------------------------------
// dense: out[r, o] = (ssp?)(in[r,:] @ W[:,o] + bias)   — 8 rows per CTA
// ---------------------------------------------------------------------------
__global__ __launch_bounds__(F_DIM) void dense_kernel(
    const float* __restrict__ in, const float* __restrict__ W,
    const float* __restrict__ bias, float* __restrict__ outp, int apply_ssp)
{
    __shared__ float xs[8 * F_DIM];
    const int r0 = blockIdx.x * 8, o = threadIdx.x;
#pragma unroll
    for (int r = 0; r < 8; ++r)
        xs[r * F_DIM + o] = in[(size_t)(r0 + r) * F_DIM + o];
    __syncthreads();

    float a[8];
    float bb = bias ? __ldg(&bias[o]) : 0.0f;
#pragma unroll
    for (int r = 0; r < 8; ++r) a[r] = bb;
#pragma unroll 4
    for (int c = 0; c < F_DIM; ++c) {
        float w = __ldg(&W[c * F_DIM + o]);
#pragma unroll
        for (int r = 0; r < 8; ++r)
            a[r] = fmaf(xs[r * F_DIM + c], w, a[r]);
    }
#pragma unroll
    for (int r = 0; r < 8; ++r) {
        float v = apply_ssp ? ssp(a[r]) : a[r];
        outp[(size_t)(r0 + r) * F_DIM + o] = v;
    }
}

// ---------------------------------------------------------------------------
// Main: one CTA per 2 atoms (128 neighbor rows), 256 threads, 8 warps (4M x 2N).
// ---------------------------------------------------------------------------
__global__ __launch_bounds__(256, 2) void cfconv_mma(
    const float* __restrict__ f_ij,   // [B,A,N,G]
    const float* __restrict__ mask,   // [B,A,N]
    const int*   __restrict__ nbrs,   // [B,A,N]
    const float* __restrict__ b_f1,
    const float* __restrict__ b_f2)
{
    extern __shared__ char smem[];
    float* b1s    = (float*)(smem + OFF_B1);
    float* b2s    = (float*)(smem + OFF_B2);
    int*   nbr_sh = (int*)  (smem + OFF_NBR);
    float* msk_sh = (float*)(smem + OFF_MSK);
    float* fijf   = (float*)(smem + OFF_FIJ);   // frag-order f_ij
    float* hf     = (float*)(smem + OFF_H);     // frag-order h, then linear Wm

    const int tid = threadIdx.x, wid = tid >> 5, lane = tid & 31;
    const int gid = lane >> 2, tig = lane & 3;
    const int c = blockIdx.x;          // atoms 2c, 2c+1
    const int b = c >> 9;              // batch

    if (tid < 128) {
        b1s[tid]    = b_f1[tid];
        b2s[tid]    = b_f2[tid];
        nbr_sh[tid] = nbrs[(size_t)c * 128 + tid];
        msk_sh[tid] = mask[(size_t)c * 128 + tid];
    }
    // stage f_ij [128 n][64 k] -> fragment order, tf32-rounded, zero-padded
    {
        const float* fb = f_ij + (size_t)c * 128 * G_DIM;
        for (int i = tid; i < 128 * 64; i += 256) {
            int n = i >> 6, k = i & 63;
            float v = (k < G_DIM) ? tf32r(__ldg(fb + n * G_DIM + k)) : 0.0f;
            int tile = n >> 4, r = n & 15;
            int ks = k >> 3, kk = k & 7;
            fijf[((tile * 8 + ks) * 32 + (r & 7) * 4 + (kk & 3)) * 4 + (kk >> 2) * 2 + (r >> 3)] = v;
        }
    }
    __syncthreads();

    const int mt0 = (wid & 3) * 2;     // warp's first 16-row tile
    const int f0  = (wid >> 2) * 64;   // warp's 64 output cols
    const int hf64 = (wid >> 2) * 64;  // permuted-weight half offset

    // ================= GEMM1: K=64 (8 k-steps) =================
    float acc[16][4];
#pragma unroll
    for (int t = 0; t < 16; ++t) { acc[t][0]=acc[t][1]=acc[t][2]=acc[t][3]=0.f; }

    {
        const float4* af = (const float4*)fijf;
        const float4* wv = (const float4*)g_Wf1v;
#pragma unroll
        for (int ks = 0; ks < 8; ++ks) {
            uint4 a0 = ((const uint4*)af)[((mt0 + 0) * 8 + ks) * 32 + lane];
            uint4 a1 = ((const uint4*)af)[((mt0 + 1) * 8 + ks) * 32 + lane];
            int r0i = ((ks * 8 + tig) * F_DIM + hf64 + gid * 8) >> 2;
            int r1i = ((ks * 8 + tig + 4) * F_DIM + hf64 + gid * 8) >> 2;
            float4 q0 = __ldg(wv + r0i), q1 = __ldg(wv + r0i + 1);
            float4 s0 = __ldg(wv + r1i), s1 = __ldg(wv + r1i + 1);
            const uint32_t* qb = (const uint32_t*)&q0;   // q0,q1 adjacent on stack? no —
            uint32_t bq[8] = {__float_as_uint(q0.x),__float_as_uint(q0.y),__float_as_uint(q0.z),__float_as_uint(q0.w),
                              __float_as_uint(q1.x),__float_as_uint(q1.y),__float_as_uint(q1.z),__float_as_uint(q1.w)};
            uint32_t bs[8] = {__float_as_uint(s0.x),__float_as_uint(s0.y),__float_as_uint(s0.z),__float_as_uint(s0.w),
                              __float_as_uint(s1.x),__float_as_uint(s1.y),__float_as_uint(s1.z),__float_as_uint(s1.w)};
            (void)qb;
#pragma unroll
            for (int ni = 0; ni < 8; ++ni) {
                mma8(acc[0 * 8 + ni], (const uint32_t*)&a0, bq[ni], bs[ni]);
                mma8(acc[1 * 8 + ni], (const uint32_t*)&a1, bq[ni], bs[ni]);
            }
        }
    }

    // ---- epi1: h = tf32(ssp(D1 + b1)) -> fragment-order SMEM (16 k-steps) ----
#pragma unroll
    for (int mi = 0; mi < 2; ++mi) {
        int tile = mt0 + mi;
#pragma unroll
        for (int ni = 0; ni < 8; ++ni) {
            float* d = acc[mi * 8 + ni];
            int f = f0 + ni * 8 + 2 * tig;
            float bb0 = b1s[f], bb1 = b1s[f + 1];
            float v00 = tf32r(ssp(d[0] + bb0));   // (gid,   f)
            float v01 = tf32r(ssp(d[1] + bb1));   // (gid,   f+1)
            float v10 = tf32r(ssp(d[2] + bb0));   // (gid+8, f)
            float v11 = tf32r(ssp(d[3] + bb1));   // (gid+8, f+1)
            int ksb = (f0 >> 3) + ni;
            int kk0 = 2 * tig, kk1 = 2 * tig + 1;
            float* base = hf + ((tile * 16 + ksb) * 32) * 4;
            base[(gid * 4 + (kk0 & 3)) * 4 + (kk0 >> 2) * 2 + 0] = v00;
            base[(gid * 4 + (kk1 & 3)) * 4 + (kk1 >> 2) * 2 + 0] = v01;
            base[(gid * 4 + (kk0 & 3)) * 4 + (kk0 >> 2) * 2 + 1] = v10;
            base[(gid * 4 + (kk1 & 3)) * 4 + (kk1 >> 2) * 2 + 1] = v11;
        }
    }
    __syncthreads();

    // ================= GEMM2: K=128 (16 k-steps) =================
#pragma unroll
    for (int t = 0; t < 16; ++t) { acc[t][0]=acc[t][1]=acc[t][2]=acc[t][3]=0.f; }

    {
        const uint4*  af = (const uint4*)hf;
        const float4* wv = (const float4*)g_Wf2v;
#pragma unroll
        for (int ks = 0; ks < 16; ++ks) {
            uint4 a0 = af[((mt0 + 0) * 16 + ks) * 32 + lane];
            uint4 a1 = af[((mt0 + 1) * 16 + ks) * 32 + lane];
            int r0i = ((ks * 8 + tig) * F_DIM + hf64 + gid * 8) >> 2;
            int r1i = ((ks * 8 + tig + 4) * F_DIM + hf64 + gid * 8) >> 2;
            float4 q0 = __ldg(wv + r0i), q1 = __ldg(wv + r0i + 1);
            float4 s0 = __ldg(wv + r1i), s1 = __ldg(wv + r1i + 1);
            uint32_t bq[8] = {__float_as_uint(q0.x),__float_as_uint(q0.y),__float_as_uint(q0.z),__float_as_uint(q0.w),
                              __float_as_uint(q1.x),__float_as_uint(q1.y),__float_as_uint(q1.z),__float_as_uint(q1.w)};
            uint32_t bs[8] = {__float_as_uint(s0.x),__float_as_uint(s0.y),__float_as_uint(s0.z),__float_as_uint(s0.w),
                              __float_as_uint(s1.x),__float_as_uint(s1.y),__float_as_uint(s1.z),__float_as_uint(s1.w)};
#pragma unroll
            for (int ni = 0; ni < 8; ++ni) {
                mma8(acc[0 * 8 + ni], (const uint32_t*)&a0, bq[ni], bs[ni]);
                mma8(acc[1 * 8 + ni], (const uint32_t*)&a1, bq[ni], bs[ni]);
            }
        }
    }
    __syncthreads();   // all warps done reading h frags

    // ---- epi2: Wm = (D2 + b2) * mask -> linear SMEM [128][WS] (reuse hf) ----
#pragma unroll
    for (int mi = 0; mi < 2; ++mi) {
        int nb = mt0 * 16 + mi * 16;   // == (wid&3)*32 + mi*16
#pragma unroll
        for (int ni = 0; ni < 8; ++ni) {
            float* d = acc[mi * 8 + ni];
            int f = f0 + ni * 8 + 2 * tig;
            int n = nb + gid;
            float bb0 = b2s[f], bb1 = b2s[f + 1];
            float m0 = msk_sh[n], m1 = msk_sh[n + 8];
            *(float2*)&hf[n * WS + f]       = make_float2((d[0] + bb0) * m0, (d[1] + bb1) * m0);
            *(float2*)&hf[(n + 8) * WS + f] = make_float2((d[2] + bb0) * m1, (d[3] + bb1) * m1);
        }
    }
    __syncthreads();

    // ---- reduce: y[atom, f] = sum_n Wm[n,f] * xw[nbr[n], f] ----
    {
        const int at = tid >> 7, f = tid & 127;
        const float* xwb = g_xw + (size_t)b * A_DIM * F_DIM + f;
        float y = 0.0f;
#pragma unroll 8
        for (int j = 0; j < 64; ++j) {
            int n = at * 64 + j;
            float xv = __ldg(xwb + (size_t)nbr_sh[n] * F_DIM);
            y = fmaf(hf[n * WS + f], xv, y);
        }
        g_y[(size_t)(c * 2 + at) * F_DIM + f] = y;
    }
}

// ---------------------------------------------------------------------------
// Inputs: x, pairwise_mask, neighbors, f_ij, W_f1, b_f1, W_f2, b_f2,
//         W_in2f, W_f2out, b_f2out
// ---------------------------------------------------------------------------
extern "C" void kernel_launch(void* const* d_in, const int* in_sizes, int n_in,
                              void* d_out, int out_size)
{
    const float* x      = (const float*)d_in[0];
    const float* mask   = (const float*)d_in[1];
    const int*   nbrs   = (const int*)  d_in[2];
    const float* f_ij   = (const float*)d_in[3];
    const float* W_f1   = (const float*)d_in[4];
    const float* b_f1   = (const float*)d_in[5];
    const float* W_f2   = (const float*)d_in[6];
    const float* b_f2   = (const float*)d_in[7];
    const float* W_in2f = (const float*)d_in[8];
    const float* W_out  = (const float*)d_in[9];
    const float* b_out  = (const float*)d_in[10];
    float*       out    = (float*)d_out;

    const int BA = in_sizes[0] / F_DIM;   // 8192

    static float* xw_ptr = nullptr;
    static float* y_ptr  = nullptr;
    if (!xw_ptr) { cudaGetSymbolAddress((void**)&xw_ptr, g_xw);
                   cudaGetSymbolAddress((void**)&y_ptr,  g_y); }

    cudaFuncSetAttribute(cfconv_mma, cudaFuncAttributeMaxDynamicSharedMemorySize, SMEM_TOTAL);

    prep_kernel<<<1, 256>>>(W_f1, W_f2);
    dense_kernel<<<BA / 8, F_DIM>>>(x, W_in2f, nullptr, xw_ptr, 0);     // xw = x @ W_in2f
    cfconv_mma<<<BA / 2, 256, SMEM_TOTAL>>>(f_ij, mask, nbrs, b_f1, b_f2);
    dense_kernel<<<BA / 8, F_DIM>>>(y_ptr, W_out, b_out, out, 1);       // out = ssp(y @ W_out + b)
}